// round 1
// baseline (speedup 1.0000x reference)
#include <cuda_runtime.h>

#define USER_NUM 100000
#define ITEM_NUM 50000
#define N_NODES  150000
#define HD       64
#define N_EDGES  4000000

// ---- scratch (no allocation allowed -> __device__ globals) ----
__device__ int   d_deg_out[N_NODES];
__device__ int   d_deg_in[N_NODES];
__device__ int   d_ptr[N_NODES + 1];
__device__ int   d_cursor[N_NODES];
__device__ int   d_esrc[N_EDGES];
__device__ float d_onorm[N_NODES];
__device__ float d_inorm[N_NODES];
__device__ float d_gA[N_NODES * HD];
__device__ float d_gB[N_NODES * HD];

// 1) zero degree counters
__global__ void k_zero_deg() {
    int i = blockIdx.x * blockDim.x + threadIdx.x;
    if (i < N_NODES) { d_deg_out[i] = 0; d_deg_in[i] = 0; }
}

// 2) degree histograms
__global__ void k_hist(const int* __restrict__ src, const int* __restrict__ dst) {
    for (int e = blockIdx.x * blockDim.x + threadIdx.x; e < N_EDGES;
         e += gridDim.x * blockDim.x) {
        atomicAdd(&d_deg_out[src[e]], 1);
        atomicAdd(&d_deg_in[dst[e]], 1);
    }
}

// 3) single-block exclusive scan of in-degrees -> CSR row ptr (+ cursor copy)
__global__ void k_scan() {
    __shared__ int sh[1024];
    const int CHUNK = (N_NODES + 1023) / 1024;  // 147
    int t = threadIdx.x;
    int beg = t * CHUNK;
    int end = beg + CHUNK; if (end > N_NODES) end = N_NODES;
    int sum = 0;
    for (int i = beg; i < end; i++) sum += d_deg_in[i];
    sh[t] = sum;
    __syncthreads();
    for (int off = 1; off < 1024; off <<= 1) {
        int v = sh[t];
        if (t >= off) v += sh[t - off];
        __syncthreads();
        sh[t] = v;
        __syncthreads();
    }
    int run = (t == 0) ? 0 : sh[t - 1];
    for (int i = beg; i < end; i++) {
        d_ptr[i] = run; d_cursor[i] = run;
        run += d_deg_in[i];
    }
    if (t == 1023) d_ptr[N_NODES] = sh[1023];
}

// 4) norms + output init + g0 = emb * out_norm   (one float4 chunk per thread)
__global__ void k_init(const float* __restrict__ user, const float* __restrict__ item,
                       float* __restrict__ out) {
    int i = blockIdx.x * blockDim.x + threadIdx.x;
    if (i >= N_NODES * (HD / 4)) return;
    int n = i >> 4;        // node
    int c = i & 15;        // float4 chunk
    float odeg = (float)d_deg_out[n]; if (odeg < 1.f) odeg = 1.f;
    float ideg = (float)d_deg_in[n];  if (ideg < 1.f) ideg = 1.f;
    float on = rsqrtf(odeg);
    if (c == 0) {
        d_onorm[n] = on;
        d_inorm[n] = rsqrtf(ideg);
    }
    const float* srcrow = (n < USER_NUM) ? (user + (size_t)n * HD)
                                         : (item + (size_t)(n - USER_NUM) * HD);
    float4 v = *(const float4*)(srcrow + c * 4);
    *(float4*)(out + (size_t)n * HD + c * 4) = v;                 // residual init
    float4 g = make_float4(v.x * on, v.y * on, v.z * on, v.w * on);
    *(float4*)(d_gA + (size_t)n * HD + c * 4) = g;                // g0
}

// 5) scatter edges into CSR buckets by dst
__global__ void k_scatter(const int* __restrict__ src, const int* __restrict__ dst) {
    for (int e = blockIdx.x * blockDim.x + threadIdx.x; e < N_EDGES;
         e += gridDim.x * blockDim.x) {
        int d = dst[e];
        int pos = atomicAdd(&d_cursor[d], 1);
        d_esrc[pos] = src[e];
    }
}

// 6) per-layer aggregation: one warp per dst node, no atomics.
//    gin pre-scaled by out_norm.  out += sum*in_norm*scale ; gout = sum*in_norm*out_norm
__global__ void k_agg(int flip, float* __restrict__ out, float scale) {
    const float* __restrict__ gin = flip ? d_gB : d_gA;
    float*       __restrict__ gout = flip ? d_gA : d_gB;

    int warp = (blockIdx.x * blockDim.x + threadIdx.x) >> 5;
    int lane = threadIdx.x & 31;
    if (warp >= N_NODES) return;
    int n = warp;

    int p0 = d_ptr[n], p1 = d_ptr[n + 1];
    float2 acc = make_float2(0.f, 0.f);

    for (int base = p0; base < p1; base += 32) {
        int cnt = p1 - base; if (cnt > 32) cnt = 32;
        int e = (lane < cnt) ? d_esrc[base + lane] : 0;
        #pragma unroll 4
        for (int j = 0; j < cnt; j++) {
            int s = __shfl_sync(0xffffffffu, e, j);
            float2 v = *(const float2*)(gin + (size_t)s * HD + lane * 2);
            acc.x += v.x;
            acc.y += v.y;
        }
    }

    float inn = d_inorm[n];
    float onn = d_onorm[n];
    float ex = acc.x * inn, ey = acc.y * inn;

    size_t o = (size_t)n * HD + lane * 2;
    float2 ov = *(float2*)(out + o);
    ov.x += ex * scale;
    ov.y += ey * scale;
    *(float2*)(out + o) = ov;

    float2 gv = make_float2(ex * onn, ey * onn);
    *(float2*)(gout + o) = gv;
}

extern "C" void kernel_launch(void* const* d_in, const int* in_sizes, int n_in,
                              void* d_out, int out_size) {
    const float* user = (const float*)d_in[0];
    const float* item = (const float*)d_in[1];
    const int*   src  = (const int*)d_in[2];
    const int*   dst  = (const int*)d_in[3];
    float*       out  = (float*)d_out;

    k_zero_deg<<<(N_NODES + 255) / 256, 256>>>();
    k_hist<<<4096, 256>>>(src, dst);
    k_scan<<<1, 1024>>>();
    k_init<<<(N_NODES * (HD / 4) + 255) / 256, 256>>>(user, item, out);
    k_scatter<<<4096, 256>>>(src, dst);

    const int AGG_BLOCKS = (N_NODES * 32) / 256;  // 18750, exact
    k_agg<<<AGG_BLOCKS, 256>>>(0, out, 1.0f / 2.0f);  // layer 0: gA -> gB
    k_agg<<<AGG_BLOCKS, 256>>>(1, out, 1.0f / 3.0f);  // layer 1: gB -> gA
    k_agg<<<AGG_BLOCKS, 256>>>(0, out, 1.0f / 4.0f);  // layer 2: gA -> gB
}

// round 3
// speedup vs baseline: 1.0607x; 1.0607x over previous
#include <cuda_runtime.h>
#include <cuda_fp16.h>

#define USER_NUM 100000
#define ITEM_NUM 50000
#define N_NODES  150000
#define HD       64
#define N_EDGES  4000000

// ---- scratch (no allocation allowed -> __device__ globals) ----
__device__ int     d_deg_out[N_NODES];
__device__ int     d_deg_in[N_NODES];
__device__ int     d_ptr[N_NODES + 1];
__device__ int     d_cursor[N_NODES];
__device__ int     d_esrc[N_EDGES];          // pre-shifted: src*32 (half2 row base)
__device__ float   d_onorm[N_NODES];
__device__ float   d_inorm[N_NODES];
__device__ __half2 d_gA[N_NODES * 32];
__device__ __half2 d_gB[N_NODES * 32];

// 1) zero degree counters
__global__ void k_zero_deg() {
    int i = blockIdx.x * blockDim.x + threadIdx.x;
    if (i < N_NODES) { d_deg_out[i] = 0; d_deg_in[i] = 0; }
}

// 2) degree histograms (int4-vectorized edge reads, grid-stride)
__global__ void k_hist(const int4* __restrict__ src4, const int4* __restrict__ dst4) {
    for (int i = blockIdx.x * blockDim.x + threadIdx.x; i < N_EDGES / 4;
         i += gridDim.x * blockDim.x) {
        int4 s = src4[i];
        int4 d = dst4[i];
        atomicAdd(&d_deg_out[s.x], 1); atomicAdd(&d_deg_out[s.y], 1);
        atomicAdd(&d_deg_out[s.z], 1); atomicAdd(&d_deg_out[s.w], 1);
        atomicAdd(&d_deg_in[d.x], 1);  atomicAdd(&d_deg_in[d.y], 1);
        atomicAdd(&d_deg_in[d.z], 1);  atomicAdd(&d_deg_in[d.w], 1);
    }
}

// 3) single-block exclusive scan of in-degrees -> CSR row ptr (+ cursor copy)
__global__ void k_scan() {
    __shared__ int sh[1024];
    const int CHUNK = (N_NODES + 1023) / 1024;  // 147
    int t = threadIdx.x;
    int beg = t * CHUNK;
    int end = beg + CHUNK; if (end > N_NODES) end = N_NODES;
    int sum = 0;
    for (int i = beg; i < end; i++) sum += d_deg_in[i];
    sh[t] = sum;
    __syncthreads();
    for (int off = 1; off < 1024; off <<= 1) {
        int v = sh[t];
        if (t >= off) v += sh[t - off];
        __syncthreads();
        sh[t] = v;
        __syncthreads();
    }
    int run = (t == 0) ? 0 : sh[t - 1];
    for (int i = beg; i < end; i++) {
        d_ptr[i] = run; d_cursor[i] = run;
        run += d_deg_in[i];
    }
    if (t == 1023) d_ptr[N_NODES] = sh[1023];
}

// 4) norms + output init + g0 = half(emb * out_norm)  (one float4 chunk per thread)
__global__ void k_init(const float* __restrict__ user, const float* __restrict__ item,
                       float* __restrict__ out) {
    int i = blockIdx.x * blockDim.x + threadIdx.x;
    if (i >= N_NODES * (HD / 4)) return;
    int n = i >> 4;        // node
    int c = i & 15;        // float4 chunk
    float odeg = (float)d_deg_out[n]; if (odeg < 1.f) odeg = 1.f;
    float ideg = (float)d_deg_in[n];  if (ideg < 1.f) ideg = 1.f;
    float on = rsqrtf(odeg);
    if (c == 0) {
        d_onorm[n] = on;
        d_inorm[n] = rsqrtf(ideg);
    }
    const float* srcrow = (n < USER_NUM) ? (user + (size_t)n * HD)
                                         : (item + (size_t)(n - USER_NUM) * HD);
    float4 v = *(const float4*)(srcrow + c * 4);
    *(float4*)(out + (size_t)n * HD + c * 4) = v;                 // residual init
    int gi = n * 32 + c * 2;
    d_gA[gi]     = __floats2half2_rn(v.x * on, v.y * on);
    d_gA[gi + 1] = __floats2half2_rn(v.z * on, v.w * on);
}

// 5) scatter edges into CSR buckets by dst (store pre-shifted src row base)
__global__ void k_scatter(const int4* __restrict__ src4, const int4* __restrict__ dst4) {
    for (int i = blockIdx.x * blockDim.x + threadIdx.x; i < N_EDGES / 4;
         i += gridDim.x * blockDim.x) {
        int4 s = src4[i];
        int4 d = dst4[i];
        d_esrc[atomicAdd(&d_cursor[d.x], 1)] = s.x << 5;
        d_esrc[atomicAdd(&d_cursor[d.y], 1)] = s.y << 5;
        d_esrc[atomicAdd(&d_cursor[d.z], 1)] = s.z << 5;
        d_esrc[atomicAdd(&d_cursor[d.w], 1)] = s.w << 5;
    }
}

// 6) per-layer aggregation: one warp per dst node, no atomics.
//    gin is half2, pre-scaled by out_norm.
//    out += sum*in_norm*scale ; gout = half(sum*in_norm*out_norm)
template <bool WRITE_G>
__global__ void k_agg(int flip, float* __restrict__ out, float scale) {
    const __half2* __restrict__ gin  = flip ? d_gB : d_gA;
    __half2*       __restrict__ gout = flip ? d_gA : d_gB;

    int warp = (blockIdx.x * blockDim.x + threadIdx.x) >> 5;
    int lane = threadIdx.x & 31;
    if (warp >= N_NODES) return;
    int n = warp;

    int p0 = d_ptr[n], p1 = d_ptr[n + 1];
    float accx = 0.f, accy = 0.f;

    for (int base = p0; base < p1; base += 32) {
        int cnt = p1 - base; if (cnt > 32) cnt = 32;
        int e = (lane < cnt) ? d_esrc[base + lane] : 0;
        #pragma unroll 8
        for (int j = 0; j < cnt; j++) {
            int s = __shfl_sync(0xffffffffu, e, j);
            float2 v = __half22float2(__ldg(gin + s + lane));
            accx += v.x;
            accy += v.y;
        }
    }

    float inn = d_inorm[n];
    float ex = accx * inn, ey = accy * inn;

    size_t o = (size_t)n * HD + lane * 2;
    float2 ov = *(float2*)(out + o);
    ov.x += ex * scale;
    ov.y += ey * scale;
    *(float2*)(out + o) = ov;

    if (WRITE_G) {
        float onn = d_onorm[n];
        gout[n * 32 + lane] = __floats2half2_rn(ex * onn, ey * onn);
    }
}

extern "C" void kernel_launch(void* const* d_in, const int* in_sizes, int n_in,
                              void* d_out, int out_size) {
    const float* user = (const float*)d_in[0];
    const float* item = (const float*)d_in[1];
    const int4*  src4 = (const int4*)d_in[2];
    const int4*  dst4 = (const int4*)d_in[3];
    float*       out  = (float*)d_out;

    const int EV_BLOCKS = (N_EDGES / 4 + 255) / 256;  // 3907

    k_zero_deg<<<(N_NODES + 255) / 256, 256>>>();
    k_hist<<<EV_BLOCKS, 256>>>(src4, dst4);
    k_scan<<<1, 1024>>>();
    k_init<<<(N_NODES * (HD / 4) + 255) / 256, 256>>>(user, item, out);
    k_scatter<<<EV_BLOCKS, 256>>>(src4, dst4);

    const int AGG_BLOCKS = (N_NODES * 32) / 256;  // 18750, exact
    k_agg<true ><<<AGG_BLOCKS, 256>>>(0, out, 1.0f / 2.0f);  // layer 0: gA -> gB
    k_agg<true ><<<AGG_BLOCKS, 256>>>(1, out, 1.0f / 3.0f);  // layer 1: gB -> gA
    k_agg<false><<<AGG_BLOCKS, 256>>>(0, out, 1.0f / 4.0f);  // layer 2: gA -> (skip)
}

// round 4
// speedup vs baseline: 1.0986x; 1.0358x over previous
#include <cuda_runtime.h>
#include <cuda_fp16.h>

#define USER_NUM 100000
#define ITEM_NUM 50000
#define N_NODES  150000
#define HD       64
#define N_EDGES  4000000

// ---- scratch (no allocation allowed -> __device__ globals) ----
__device__ int     d_deg_out[N_NODES];
__device__ int     d_deg_in[N_NODES];
__device__ int     d_ptr[N_NODES + 1];
__device__ int     d_cursor[N_NODES];
__device__ int     d_esrc[N_EDGES];          // pre-shifted: src*8 (int4 row base)
__device__ float   d_onorm[N_NODES];
__device__ float   d_inorm[N_NODES];
__device__ __half2 d_gA[N_NODES * 32];       // row = 64 half = 8 int4
__device__ __half2 d_gB[N_NODES * 32];

// 1) zero degree counters
__global__ void k_zero_deg() {
    int i = blockIdx.x * blockDim.x + threadIdx.x;
    if (i < N_NODES) { d_deg_out[i] = 0; d_deg_in[i] = 0; }
}

// 2) degree histograms (int4-vectorized edge reads)
__global__ void k_hist(const int4* __restrict__ src4, const int4* __restrict__ dst4) {
    int i = blockIdx.x * blockDim.x + threadIdx.x;
    if (i >= N_EDGES / 4) return;
    int4 s = src4[i];
    int4 d = dst4[i];
    atomicAdd(&d_deg_out[s.x], 1); atomicAdd(&d_deg_out[s.y], 1);
    atomicAdd(&d_deg_out[s.z], 1); atomicAdd(&d_deg_out[s.w], 1);
    atomicAdd(&d_deg_in[d.x], 1);  atomicAdd(&d_deg_in[d.y], 1);
    atomicAdd(&d_deg_in[d.z], 1);  atomicAdd(&d_deg_in[d.w], 1);
}

// 3) single-block exclusive scan of in-degrees -> CSR row ptr (+ cursor copy)
__global__ void k_scan() {
    __shared__ int sh[1024];
    const int CHUNK = (N_NODES + 1023) / 1024;  // 147
    int t = threadIdx.x;
    int beg = t * CHUNK;
    int end = beg + CHUNK; if (end > N_NODES) end = N_NODES;
    int sum = 0;
    for (int i = beg; i < end; i++) sum += d_deg_in[i];
    sh[t] = sum;
    __syncthreads();
    for (int off = 1; off < 1024; off <<= 1) {
        int v = sh[t];
        if (t >= off) v += sh[t - off];
        __syncthreads();
        sh[t] = v;
        __syncthreads();
    }
    int run = (t == 0) ? 0 : sh[t - 1];
    for (int i = beg; i < end; i++) {
        d_ptr[i] = run; d_cursor[i] = run;
        run += d_deg_in[i];
    }
    if (t == 1023) d_ptr[N_NODES] = sh[1023];
}

// 4) norms + output init + g0 = half(emb * out_norm)  (one float4 chunk per thread)
__global__ void k_init(const float* __restrict__ user, const float* __restrict__ item,
                       float* __restrict__ out) {
    int i = blockIdx.x * blockDim.x + threadIdx.x;
    if (i >= N_NODES * (HD / 4)) return;
    int n = i >> 4;        // node
    int c = i & 15;        // float4 chunk
    float odeg = (float)d_deg_out[n]; if (odeg < 1.f) odeg = 1.f;
    float ideg = (float)d_deg_in[n];  if (ideg < 1.f) ideg = 1.f;
    float on = rsqrtf(odeg);
    if (c == 0) {
        d_onorm[n] = on;
        d_inorm[n] = rsqrtf(ideg);
    }
    const float* srcrow = (n < USER_NUM) ? (user + (size_t)n * HD)
                                         : (item + (size_t)(n - USER_NUM) * HD);
    float4 v = *(const float4*)(srcrow + c * 4);
    *(float4*)(out + (size_t)n * HD + c * 4) = v;                 // residual init
    int gi = n * 32 + c * 2;
    d_gA[gi]     = __floats2half2_rn(v.x * on, v.y * on);
    d_gA[gi + 1] = __floats2half2_rn(v.z * on, v.w * on);
}

// 5) scatter edges into CSR buckets by dst (store pre-shifted int4 row base)
__global__ void k_scatter(const int4* __restrict__ src4, const int4* __restrict__ dst4) {
    int i = blockIdx.x * blockDim.x + threadIdx.x;
    if (i >= N_EDGES / 4) return;
    int4 s = src4[i];
    int4 d = dst4[i];
    d_esrc[atomicAdd(&d_cursor[d.x], 1)] = s.x << 3;
    d_esrc[atomicAdd(&d_cursor[d.y], 1)] = s.y << 3;
    d_esrc[atomicAdd(&d_cursor[d.z], 1)] = s.z << 3;
    d_esrc[atomicAdd(&d_cursor[d.w], 1)] = s.w << 3;
}

// 6) per-layer aggregation: one warp per dst node, 4 edges in flight.
//    Lane = (grp = lane>>3, sub = lane&7). Group g handles edge j*4+g;
//    each lane loads int4 = 8 dims (4 half2). Cross-group shfl_xor reduce at end.
template <bool WRITE_G>
__global__ void k_agg(int flip, float* __restrict__ out, float scale) {
    const int4* __restrict__ gin4  = flip ? (const int4*)d_gB : (const int4*)d_gA;
    int4*       __restrict__ gout4 = flip ? (int4*)d_gA : (int4*)d_gB;

    int warp = (blockIdx.x * blockDim.x + threadIdx.x) >> 5;
    int lane = threadIdx.x & 31;
    if (warp >= N_NODES) return;
    int n   = warp;
    int grp = lane >> 3;
    int sub = lane & 7;

    int p0 = d_ptr[n], p1 = d_ptr[n + 1];
    float acc[8];
    #pragma unroll
    for (int k = 0; k < 8; k++) acc[k] = 0.f;

    for (int base = p0; base < p1; base += 32) {
        int navail = p1 - base; if (navail > 32) navail = 32;
        int e = (lane < navail) ? d_esrc[base + lane] : 0;
        int iters = (navail + 3) >> 2;
        #pragma unroll 4
        for (int j = 0; j < iters; j++) {
            int idx = j * 4 + grp;
            int s = __shfl_sync(0xffffffffu, e, idx & 31);
            if (idx < navail) {
                int4 r = __ldg(gin4 + s + sub);
                float2 f0 = __half22float2(*(__half2*)&r.x);
                float2 f1 = __half22float2(*(__half2*)&r.y);
                float2 f2 = __half22float2(*(__half2*)&r.z);
                float2 f3 = __half22float2(*(__half2*)&r.w);
                acc[0] += f0.x; acc[1] += f0.y;
                acc[2] += f1.x; acc[3] += f1.y;
                acc[4] += f2.x; acc[5] += f2.y;
                acc[6] += f3.x; acc[7] += f3.y;
            }
        }
    }

    // cross-group reduction (groups differ in lane bits 3,4)
    #pragma unroll
    for (int k = 0; k < 8; k++) {
        acc[k] += __shfl_xor_sync(0xffffffffu, acc[k], 8);
        acc[k] += __shfl_xor_sync(0xffffffffu, acc[k], 16);
    }

    float inn = d_inorm[n];
    float ex[8];
    #pragma unroll
    for (int k = 0; k < 8; k++) ex[k] = acc[k] * inn;

    // out += ex*scale : 16 lanes (grp 0,1) each RMW one float4; covers full 256B row
    if (grp < 2) {
        float4* outrow = (float4*)(out + (size_t)n * HD);
        int q = sub * 2 + grp;              // float4 index 0..15
        int o = grp * 4;                    // acc offset
        float4 ov = outrow[q];
        ov.x += ex[o + 0] * scale;
        ov.y += ex[o + 1] * scale;
        ov.z += ex[o + 2] * scale;
        ov.w += ex[o + 3] * scale;
        outrow[q] = ov;
    }

    // gout = half(ex * out_norm) : 8 lanes (grp 0) each store one int4 (8 dims)
    if (WRITE_G && grp == 0) {
        float onn = d_onorm[n];
        __half2 h0 = __floats2half2_rn(ex[0] * onn, ex[1] * onn);
        __half2 h1 = __floats2half2_rn(ex[2] * onn, ex[3] * onn);
        __half2 h2 = __floats2half2_rn(ex[4] * onn, ex[5] * onn);
        __half2 h3 = __floats2half2_rn(ex[6] * onn, ex[7] * onn);
        int4 r;
        r.x = *(int*)&h0; r.y = *(int*)&h1; r.z = *(int*)&h2; r.w = *(int*)&h3;
        gout4[n * 8 + sub] = r;
    }
}

extern "C" void kernel_launch(void* const* d_in, const int* in_sizes, int n_in,
                              void* d_out, int out_size) {
    const float* user = (const float*)d_in[0];
    const float* item = (const float*)d_in[1];
    const int4*  src4 = (const int4*)d_in[2];
    const int4*  dst4 = (const int4*)d_in[3];
    float*       out  = (float*)d_out;

    const int EV_BLOCKS = (N_EDGES / 4 + 255) / 256;  // 3907

    k_zero_deg<<<(N_NODES + 255) / 256, 256>>>();
    k_hist<<<EV_BLOCKS, 256>>>(src4, dst4);
    k_scan<<<1, 1024>>>();
    k_init<<<(N_NODES * (HD / 4) + 255) / 256, 256>>>(user, item, out);
    k_scatter<<<EV_BLOCKS, 256>>>(src4, dst4);

    const int AGG_BLOCKS = (N_NODES * 32) / 256;  // 18750, exact
    k_agg<true ><<<AGG_BLOCKS, 256>>>(0, out, 1.0f / 2.0f);  // layer 0: gA -> gB
    k_agg<true ><<<AGG_BLOCKS, 256>>>(1, out, 1.0f / 3.0f);  // layer 1: gB -> gA
    k_agg<false><<<AGG_BLOCKS, 256>>>(0, out, 1.0f / 4.0f);  // layer 2: gA -> (skip)
}